// round 1
// baseline (speedup 1.0000x reference)
#include <cuda_runtime.h>
#include <cstdint>

#define SEQ   2048
#define D_IN  300
#define UDIM  150
#define ZDIM  600
#define H1    300
#define NSYN  4
#define TS    16

// ---------------- scratch (no cudaMalloc allowed) ----------------
__device__ float g_X[2][SEQ*ZDIM];     // x@Wk + b, per direction
__device__ float g_hidden[SEQ*H1];     // [hf | hb]
__device__ float g_out[SEQ*H1];        // hidden@W1 + b1
__device__ float g_wbuf[SEQ*H1];       // c2[s]*h_hat[s]

__device__ __forceinline__ uint32_t smem_u32(const void* p){
  uint32_t a;
  asm("{ .reg .u64 t; cvta.to.shared.u64 t, %1; cvt.u32.u64 %0, t; }" : "=r"(a) : "l"(p));
  return a;
}

// ---------------- Kernel A: X[dir] = emb@Wk_dir + b_dir ----------------
__global__ __launch_bounds__(608) void proj_kernel(
    const int* __restrict__ sentence,
    const float* __restrict__ E,
    const float* __restrict__ Wk_f, const float* __restrict__ b_f,
    const float* __restrict__ Wk_b, const float* __restrict__ b_b)
{
  int dir = blockIdx.y;
  const float* __restrict__ Wk = dir ? Wk_b : Wk_f;
  const float* __restrict__ bb = dir ? b_b : b_f;
  __shared__ __align__(16) float semb[TS*D_IN];
  __shared__ int srow[TS];
  int tid = threadIdx.x;
  int t0 = blockIdx.x * TS;
  if (tid < TS) srow[tid] = sentence[t0 + tid];
  __syncthreads();
  for (int e = tid; e < TS*D_IN; e += blockDim.x) {
    int s = e / D_IN, d = e - s*D_IN;
    semb[e] = E[(long)srow[s]*D_IN + d];
  }
  __syncthreads();
  if (tid >= ZDIM) return;
  int col = tid;
  float acc[TS];
  float bv = bb[col];
  #pragma unroll
  for (int s=0;s<TS;s++) acc[s]=bv;
  for (int k=0;k<D_IN;k+=4){
    float w0 = Wk[(k+0)*ZDIM+col];
    float w1 = Wk[(k+1)*ZDIM+col];
    float w2 = Wk[(k+2)*ZDIM+col];
    float w3 = Wk[(k+3)*ZDIM+col];
    #pragma unroll
    for (int s=0;s<TS;s++){
      float4 e4 = *reinterpret_cast<const float4*>(&semb[s*D_IN+k]);
      acc[s] += e4.x*w0 + e4.y*w1 + e4.z*w2 + e4.w*w3;
    }
  }
  #pragma unroll
  for (int s=0;s<TS;s++)
    g_X[dir][(long)(t0+s)*ZDIM + col] = acc[s];
}

// ---------------- Kernel LSTM: cluster of 2 CTAs per direction ----------------
// CTA `rank` owns units [rank*75, rank*75+75). Each of 600 active threads
// owns half of one z-column's recurrent weights (75 fp32 in registers).
struct LSmem {
  float h[2][160];       // double-buffered full h[150]
  float partial[304];    // half-1 partial dot products
  float z[304];          // assembled pre-activations (local 300 columns)
};

__global__ void __cluster_dims__(2,1,1) __launch_bounds__(608,1)
lstm_kernel(const float* __restrict__ Wr_f, const float* __restrict__ Wr_b)
{
  __shared__ LSmem sm;
  int tid = threadIdx.x;
  int dir = blockIdx.x >> 1;
  uint32_t rank;
  asm("mov.u32 %0, %%cluster_ctarank;" : "=r"(rank));
  const float* __restrict__ Wr = dir ? Wr_b : Wr_f;
  const float* __restrict__ X  = g_X[dir];

  bool active = tid < 600;
  int half = tid / 300;          // which 75 h-entries this thread consumes
  int c    = tid % 300;          // local column 0..299
  int gate = c / 75;             // i,f,g,o
  int u    = c - gate*75;        // unit within this CTA's 75
  int G    = gate*150 + (int)rank*75 + u;   // global z column 0..599

  float w[75];
  if (active){
    #pragma unroll
    for (int j=0;j<75;j++) w[j] = Wr[(half*75+j)*ZDIM + G];
  }
  for (int i=tid;i<160;i+=608){ sm.h[0][i]=0.f; sm.h[1][i]=0.f; }
  float creg = 0.f;
  uint32_t peer = rank ^ 1u;

  asm volatile("barrier.cluster.arrive.aligned;" ::: "memory");
  asm volatile("barrier.cluster.wait.aligned;"   ::: "memory");

  for (int ts=0; ts<SEQ; ts++){
    int t = dir ? (SEQ-1-ts) : ts;
    int rb = ts & 1;
    float x = 0.f;
    if (active && half==0) x = X[(long)t*ZDIM + G];   // overlaps with FMA loop
    float a0=0.f,a1=0.f,a2=0.f;
    if (active){
      const float* hb = &sm.h[rb][half*75];
      #pragma unroll
      for (int j=0;j<75;j+=3){
        a0 += w[j+0]*hb[j+0];
        a1 += w[j+1]*hb[j+1];
        a2 += w[j+2]*hb[j+2];
      }
    }
    if (active && half==1) sm.partial[c] = a0+a1+a2;
    __syncthreads();
    if (active && half==0) sm.z[c] = x + a0+a1+a2 + sm.partial[c];
    __syncthreads();
    if (tid < 75){
      float zi = sm.z[tid];
      float zf = sm.z[75+tid];
      float zg = sm.z[150+tid];
      float zo = sm.z[225+tid];
      float ig = 1.f/(1.f+expf(-zi));
      float fg = 1.f/(1.f+expf(-zf));
      float gg = tanhf(zg);
      float og = 1.f/(1.f+expf(-zo));
      creg = fg*creg + ig*gg;
      float h = og*tanhf(creg);
      int wb = rb^1;
      int hi = (int)rank*75 + tid;
      sm.h[wb][hi] = h;
      uint32_t laddr = smem_u32(&sm.h[wb][hi]);
      uint32_t raddr;
      asm("mapa.shared::cluster.u32 %0, %1, %2;" : "=r"(raddr) : "r"(laddr), "r"(peer));
      asm volatile("st.shared::cluster.f32 [%0], %1;" :: "r"(raddr), "f"(h) : "memory");
      g_hidden[(long)t*H1 + dir*UDIM + hi] = h;
    }
    // release: makes the DSMEM h-stores visible cluster-wide for next step
    asm volatile("barrier.cluster.arrive.aligned;" ::: "memory");
    asm volatile("barrier.cluster.wait.aligned;"   ::: "memory");
  }
}

// ---------------- Kernel B: out = hidden@W1 + b1 ----------------
__global__ __launch_bounds__(320) void out_kernel(
    const float* __restrict__ W1, const float* __restrict__ b1)
{
  __shared__ __align__(16) float shid[TS*H1];
  int tid = threadIdx.x;
  int t0 = blockIdx.x * TS;
  for (int e=tid; e<TS*H1; e+=blockDim.x)
    shid[e] = g_hidden[(long)t0*H1 + e];
  __syncthreads();
  if (tid >= H1) return;
  int col = tid;
  float acc[TS];
  float bv = b1[col];
  #pragma unroll
  for (int s=0;s<TS;s++) acc[s]=bv;
  for (int k=0;k<H1;k+=4){
    float w0=W1[(k+0)*H1+col], w1=W1[(k+1)*H1+col];
    float w2=W1[(k+2)*H1+col], w3=W1[(k+3)*H1+col];
    #pragma unroll
    for (int s=0;s<TS;s++){
      float4 e4 = *reinterpret_cast<const float4*>(&shid[s*H1+k]);
      acc[s] += e4.x*w0+e4.y*w1+e4.z*w2+e4.w*w3;
    }
  }
  #pragma unroll
  for (int s=0;s<TS;s++) g_out[(long)(t0+s)*H1+col]=acc[s];
}

// ---------------- Kernel C: synonym attention per token ----------------
__global__ __launch_bounds__(128) void attn_kernel(
    const int* __restrict__ sentence,
    const int* __restrict__ syn_idx,
    const float* __restrict__ E,
    const float* __restrict__ W2, const float* __restrict__ b2)
{
  int s = blockIdx.x;
  int ids = (s==0)?0:(s-1);
  int tid = threadIdx.x;
  __shared__ float sout[H1], ssyn[NSYN*H1], shh[H1], red[128], scoef[NSYN], sc2;
  __shared__ int srow[NSYN];
  int token = sentence[s];
  if (tid < NSYN) srow[tid] = syn_idx[token*NSYN+tid];
  for (int d=tid; d<H1; d+=128) sout[d] = g_out[(long)ids*H1+d];
  __syncthreads();
  for (int e=tid; e<NSYN*H1; e+=128){
    int k=e/H1, d=e-k*H1;
    ssyn[e] = E[(long)srow[k]*D_IN + d];
  }
  __syncthreads();
  float p0=0,p1=0,p2=0,p3=0;
  for (int d=tid; d<H1; d+=128){
    float o = sout[d];
    p0 += ssyn[d]*o; p1 += ssyn[H1+d]*o; p2 += ssyn[2*H1+d]*o; p3 += ssyn[3*H1+d]*o;
  }
  float pv[4]={p0,p1,p2,p3};
  #pragma unroll
  for (int k=0;k<4;k++){
    red[tid]=pv[k]; __syncthreads();
    for (int off=64; off>0; off>>=1){
      if(tid<off) red[tid]+=red[tid+off];
      __syncthreads();
    }
    if (tid==0) scoef[k]=expf(red[0]);
    __syncthreads();
  }
  float q=0.f;
  for (int d=tid; d<H1; d+=128){
    float hh = scoef[0]*ssyn[d]+scoef[1]*ssyn[H1+d]
             + scoef[2]*ssyn[2*H1+d]+scoef[3]*ssyn[3*H1+d]
             + g_hidden[(long)ids*H1+d];
    shh[d]=hh;
    q += hh*W2[d];
  }
  red[tid]=q; __syncthreads();
  for (int off=64; off>0; off>>=1){
    if(tid<off) red[tid]+=red[tid+off];
    __syncthreads();
  }
  if (tid==0) sc2 = expf(tanhf(red[0]+b2[0]));
  __syncthreads();
  float c2v = sc2;
  for (int d=tid; d<H1; d+=128) g_wbuf[(long)s*H1+d] = c2v*shh[d];
}

// ---------------- Kernel D: H = sum_s wbuf[s]; logits ----------------
__global__ __launch_bounds__(320) void final_kernel(
    const float* __restrict__ We, const float* __restrict__ be,
    const float* __restrict__ Ws, const float* __restrict__ bs,
    float* __restrict__ dout)
{
  __shared__ float sH[H1];
  int tid = threadIdx.x;
  if (tid < H1){
    float a0=0,a1=0,a2=0,a3=0;
    for (int s=0;s<SEQ;s+=4){
      a0 += g_wbuf[(long)(s+0)*H1+tid];
      a1 += g_wbuf[(long)(s+1)*H1+tid];
      a2 += g_wbuf[(long)(s+2)*H1+tid];
      a3 += g_wbuf[(long)(s+3)*H1+tid];
    }
    sH[tid] = (a0+a1)+(a2+a3);
  }
  __syncthreads();
  if (tid < 9){
    float r = (tid<8)? be[tid] : bs[0];
    for (int d=0; d<H1; d++){
      float wv = (tid<8)? We[d*8+tid] : Ws[d];
      r += sH[d]*wv;
    }
    dout[tid] = r;
  }
}

// ---------------- launch ----------------
extern "C" void kernel_launch(void* const* d_in, const int* in_sizes, int n_in,
                              void* d_out, int out_size)
{
  const int*   sentence = (const int*)d_in[0];
  const int*   syn_idx  = (const int*)d_in[1];
  const float* E    = (const float*)d_in[2];
  const float* Wk_f = (const float*)d_in[3];
  const float* Wr_f = (const float*)d_in[4];
  const float* b_f  = (const float*)d_in[5];
  const float* Wk_b = (const float*)d_in[6];
  const float* Wr_b = (const float*)d_in[7];
  const float* b_b  = (const float*)d_in[8];
  const float* W1   = (const float*)d_in[9];
  const float* b1   = (const float*)d_in[10];
  const float* W2   = (const float*)d_in[11];
  const float* b2   = (const float*)d_in[12];
  const float* We   = (const float*)d_in[13];
  const float* be   = (const float*)d_in[14];
  const float* Ws   = (const float*)d_in[15];
  const float* bs   = (const float*)d_in[16];
  float* dout = (float*)d_out;

  dim3 gA(SEQ/TS, 2);
  proj_kernel<<<gA, 608>>>(sentence, E, Wk_f, b_f, Wk_b, b_b);
  lstm_kernel<<<4, 608>>>(Wr_f, Wr_b);           // 2 clusters of 2 (fwd, bwd)
  out_kernel<<<SEQ/TS, 320>>>(W1, b1);
  attn_kernel<<<SEQ, 128>>>(sentence, syn_idx, E, W2, b2);
  final_kernel<<<1, 320>>>(We, be, Ws, bs, dout);
}

// round 2
// speedup vs baseline: 1.2310x; 1.2310x over previous
#include <cuda_runtime.h>
#include <cstdint>

#define SEQ   2048
#define D_IN  300
#define UDIM  150
#define ZDIM  600
#define H1    300
#define NSYN  4
#define TS    16

// ---------------- scratch (no cudaMalloc allowed) ----------------
__device__ float g_X[2][SEQ*ZDIM];     // x@Wk + b, per direction
__device__ float g_hidden[SEQ*H1];     // [hf | hb]
__device__ float g_out[SEQ*H1];        // hidden@W1 + b1
__device__ float g_wbuf[SEQ*H1];       // c2[s]*h_hat[s]

__device__ __forceinline__ uint32_t smem_u32(const void* p){
  uint32_t a;
  asm("{ .reg .u64 t; cvta.to.shared.u64 t, %1; cvt.u32.u64 %0, t; }" : "=r"(a) : "l"(p));
  return a;
}
__device__ __forceinline__ uint64_t ffma2(uint64_t a, uint64_t b, uint64_t c){
  uint64_t d; asm("fma.rn.f32x2 %0,%1,%2,%3;" : "=l"(d) : "l"(a),"l"(b),"l"(c)); return d;
}
__device__ __forceinline__ float sigm(float x){ return __fdividef(1.f, 1.f + __expf(-x)); }
__device__ __forceinline__ float tanh_(float x){ return 1.f - __fdividef(2.f, __expf(2.f*x)+1.f); }

// ---------------- Kernel A: X[dir] = emb@Wk_dir + b_dir ----------------
__global__ __launch_bounds__(608) void proj_kernel(
    const int* __restrict__ sentence,
    const float* __restrict__ E,
    const float* __restrict__ Wk_f, const float* __restrict__ b_f,
    const float* __restrict__ Wk_b, const float* __restrict__ b_b)
{
  int dir = blockIdx.y;
  const float* __restrict__ Wk = dir ? Wk_b : Wk_f;
  const float* __restrict__ bb = dir ? b_b : b_f;
  __shared__ __align__(16) float semb[TS*D_IN];
  __shared__ int srow[TS];
  int tid = threadIdx.x;
  int t0 = blockIdx.x * TS;
  if (tid < TS) srow[tid] = sentence[t0 + tid];
  __syncthreads();
  for (int e = tid; e < TS*D_IN; e += blockDim.x) {
    int s = e / D_IN, d = e - s*D_IN;
    semb[e] = E[(long)srow[s]*D_IN + d];
  }
  __syncthreads();
  if (tid >= ZDIM) return;
  int col = tid;
  float acc[TS];
  float bv = bb[col];
  #pragma unroll
  for (int s=0;s<TS;s++) acc[s]=bv;
  for (int k=0;k<D_IN;k+=4){
    float w0 = Wk[(k+0)*ZDIM+col];
    float w1 = Wk[(k+1)*ZDIM+col];
    float w2 = Wk[(k+2)*ZDIM+col];
    float w3 = Wk[(k+3)*ZDIM+col];
    #pragma unroll
    for (int s=0;s<TS;s++){
      float4 e4 = *reinterpret_cast<const float4*>(&semb[s*D_IN+k]);
      acc[s] += e4.x*w0 + e4.y*w1 + e4.z*w2 + e4.w*w3;
    }
  }
  #pragma unroll
  for (int s=0;s<TS;s++)
    g_X[dir][(long)(t0+s)*ZDIM + col] = acc[s];
}

// ---------------- LSTM: cluster of 2 CTAs per direction ----------------
// 300 compute threads per CTA; thread c owns z-column G = gate*150 + rank*75 + u
// with all 150 recurrent weights in registers as 76 packed f32x2 pairs.
// h handoff to peer CTA via st.shared::cluster + mbarrier (no cluster barrier).
struct LSmem2 {
  float4 h[2][38];        // double-buffered h[152] (150 + 2 zero pad)
  float  z[304];
  unsigned long long mbar;
};

__global__ void __cluster_dims__(2,1,1) __launch_bounds__(320,1)
lstm_kernel(const float* __restrict__ Wr_f, const float* __restrict__ Wr_b)
{
  __shared__ LSmem2 sm;
  int tid = threadIdx.x;
  int dir = blockIdx.x >> 1;
  uint32_t rank;
  asm("mov.u32 %0, %%cluster_ctarank;" : "=r"(rank));
  uint32_t peer = rank ^ 1u;
  const float* __restrict__ Wr = dir ? Wr_b : Wr_f;
  const float* __restrict__ X  = g_X[dir];

  bool active = tid < 300;
  int gate = tid / 75;
  int u    = tid - gate*75;
  int G    = gate*150 + (int)rank*75 + u;   // global z column

  // pack recurrent weights: pair m = (Wr[2m][G], Wr[2m+1][G])
  uint64_t w2[76];
  if (active){
    #pragma unroll
    for (int m=0;m<76;m++){
      float w0 = (2*m   < UDIM) ? Wr[(2*m  )*ZDIM + G] : 0.f;
      float w1 = (2*m+1 < UDIM) ? Wr[(2*m+1)*ZDIM + G] : 0.f;
      asm("mov.b64 %0,{%1,%2};" : "=l"(w2[m]) : "f"(w0), "f"(w1));
    }
  }

  float* hraw = (float*)sm.h;
  for (int i=tid;i<2*152;i+=320) hraw[i]=0.f;

  uint32_t s_h    = smem_u32(&sm.h[0][0]);
  uint32_t s_mbar = smem_u32(&sm.mbar);
  if (tid == 0){
    asm volatile("mbarrier.init.shared.b64 [%0], %1;" :: "r"(s_mbar), "r"(150) : "memory");
  }
  __syncthreads();

  uint32_t r_h, r_mbar;
  asm("mapa.shared::cluster.u32 %0, %1, %2;" : "=r"(r_h)    : "r"(s_h),    "r"(peer));
  asm("mapa.shared::cluster.u32 %0, %1, %2;" : "=r"(r_mbar) : "r"(s_mbar), "r"(peer));

  // one-time cluster sync: peer smem (h zeros, mbar) initialized
  asm volatile("barrier.cluster.arrive.aligned;" ::: "memory");
  asm volatile("barrier.cluster.wait.aligned;"   ::: "memory");

  float creg = 0.f;

  for (int ts=0; ts<SEQ; ts++){
    int t  = dir ? (SEQ-1-ts) : ts;
    int rb = ts & 1;
    float x = 0.f;
    if (active) x = __ldg(&X[t*ZDIM + G]);

    uint64_t a0=0ull, a1=0ull, a2=0ull, a3=0ull;
    if (active){
      uint32_t ha = s_h + rb*608;   // 152 floats * 4B
      #pragma unroll
      for (int m=0;m<38;m++){
        uint64_t p0,p1;
        asm("ld.shared.v2.b64 {%0,%1},[%2];" : "=l"(p0),"=l"(p1) : "r"(ha + m*16));
        if (m & 1){ a2 = ffma2(p0, w2[2*m], a2); a3 = ffma2(p1, w2[2*m+1], a3); }
        else      { a0 = ffma2(p0, w2[2*m], a0); a1 = ffma2(p1, w2[2*m+1], a1); }
      }
      float l0,h0,l1,h1,l2,h2,l3,h3;
      asm("mov.b64 {%0,%1},%2;" : "=f"(l0),"=f"(h0) : "l"(a0));
      asm("mov.b64 {%0,%1},%2;" : "=f"(l1),"=f"(h1) : "l"(a1));
      asm("mov.b64 {%0,%1},%2;" : "=f"(l2),"=f"(h2) : "l"(a2));
      asm("mov.b64 {%0,%1},%2;" : "=f"(l3),"=f"(h3) : "l"(a3));
      sm.z[tid] = x + ((l0+h0)+(l1+h1)) + ((l2+h2)+(l3+h3));
    }
    __syncthreads();

    if (tid < 75){
      float zi = sm.z[tid];
      float zf = sm.z[75+tid];
      float zg = sm.z[150+tid];
      float zo = sm.z[225+tid];
      float ig = sigm(zi);
      float fg = sigm(zf);
      float gg = tanh_(zg);
      float og = sigm(zo);
      creg = fg*creg + ig*gg;
      float h = og*tanh_(creg);
      int wb = rb ^ 1;
      int hi = (int)rank*75 + tid;
      hraw[wb*152 + hi] = h;                           // local buffer
      uint32_t ra = r_h + (uint32_t)(wb*608 + hi*4);   // peer buffer
      asm volatile("st.shared::cluster.f32 [%0], %1;" :: "r"(ra), "f"(h) : "memory");
      g_hidden[t*H1 + dir*UDIM + hi] = h;
      asm volatile("mbarrier.arrive.release.cta.shared::cta.b64 _, [%0];"
                   :: "r"(s_mbar) : "memory");
      asm volatile("mbarrier.arrive.release.cluster.shared::cluster.b64 _, [%0];"
                   :: "r"(r_mbar) : "memory");
    }

    // wait for all 150 arrivals (75 local + 75 peer) of this step's phase
    {
      uint32_t done;
      asm volatile(
        "{\n\t.reg .pred p;\n\t"
        "mbarrier.try_wait.parity.acquire.cluster.shared::cta.b64 p, [%1], %2;\n\t"
        "selp.b32 %0, 1, 0, p;\n\t}"
        : "=r"(done) : "r"(s_mbar), "r"((uint32_t)rb) : "memory");
      if (!done){
        asm volatile(
          "{\n\t.reg .pred P1;\n\t"
          "W_%=:\n\t"
          "mbarrier.try_wait.parity.acquire.cluster.shared::cta.b64 P1, [%0], %1, 0x989680;\n\t"
          "@P1 bra.uni D_%=;\n\t"
          "bra.uni W_%=;\n\t"
          "D_%=:\n\t}"
          :: "r"(s_mbar), "r"((uint32_t)rb) : "memory");
      }
    }
  }
}

// ---------------- Kernel B: out = hidden@W1 + b1 ----------------
__global__ __launch_bounds__(320) void out_kernel(
    const float* __restrict__ W1, const float* __restrict__ b1)
{
  __shared__ __align__(16) float shid[TS*H1];
  int tid = threadIdx.x;
  int t0 = blockIdx.x * TS;
  for (int e=tid; e<TS*H1; e+=blockDim.x)
    shid[e] = g_hidden[(long)t0*H1 + e];
  __syncthreads();
  if (tid >= H1) return;
  int col = tid;
  float acc[TS];
  float bv = b1[col];
  #pragma unroll
  for (int s=0;s<TS;s++) acc[s]=bv;
  for (int k=0;k<H1;k+=4){
    float w0=W1[(k+0)*H1+col], w1=W1[(k+1)*H1+col];
    float w2=W1[(k+2)*H1+col], w3=W1[(k+3)*H1+col];
    #pragma unroll
    for (int s=0;s<TS;s++){
      float4 e4 = *reinterpret_cast<const float4*>(&shid[s*H1+k]);
      acc[s] += e4.x*w0+e4.y*w1+e4.z*w2+e4.w*w3;
    }
  }
  #pragma unroll
  for (int s=0;s<TS;s++) g_out[(long)(t0+s)*H1+col]=acc[s];
}

// ---------------- Kernel C: synonym attention per token ----------------
__global__ __launch_bounds__(128) void attn_kernel(
    const int* __restrict__ sentence,
    const int* __restrict__ syn_idx,
    const float* __restrict__ E,
    const float* __restrict__ W2, const float* __restrict__ b2)
{
  int s = blockIdx.x;
  int ids = (s==0)?0:(s-1);
  int tid = threadIdx.x;
  __shared__ float sout[H1], ssyn[NSYN*H1], shh[H1], red[128], scoef[NSYN], sc2;
  __shared__ int srow[NSYN];
  int token = sentence[s];
  if (tid < NSYN) srow[tid] = syn_idx[token*NSYN+tid];
  for (int d=tid; d<H1; d+=128) sout[d] = g_out[(long)ids*H1+d];
  __syncthreads();
  for (int e=tid; e<NSYN*H1; e+=128){
    int k=e/H1, d=e-k*H1;
    ssyn[e] = E[(long)srow[k]*D_IN + d];
  }
  __syncthreads();
  float p0=0,p1=0,p2=0,p3=0;
  for (int d=tid; d<H1; d+=128){
    float o = sout[d];
    p0 += ssyn[d]*o; p1 += ssyn[H1+d]*o; p2 += ssyn[2*H1+d]*o; p3 += ssyn[3*H1+d]*o;
  }
  float pv[4]={p0,p1,p2,p3};
  #pragma unroll
  for (int k=0;k<4;k++){
    red[tid]=pv[k]; __syncthreads();
    for (int off=64; off>0; off>>=1){
      if(tid<off) red[tid]+=red[tid+off];
      __syncthreads();
    }
    if (tid==0) scoef[k]=expf(red[0]);
    __syncthreads();
  }
  float q=0.f;
  for (int d=tid; d<H1; d+=128){
    float hh = scoef[0]*ssyn[d]+scoef[1]*ssyn[H1+d]
             + scoef[2]*ssyn[2*H1+d]+scoef[3]*ssyn[3*H1+d]
             + g_hidden[(long)ids*H1+d];
    shh[d]=hh;
    q += hh*W2[d];
  }
  red[tid]=q; __syncthreads();
  for (int off=64; off>0; off>>=1){
    if(tid<off) red[tid]+=red[tid+off];
    __syncthreads();
  }
  if (tid==0) sc2 = expf(tanhf(red[0]+b2[0]));
  __syncthreads();
  float c2v = sc2;
  for (int d=tid; d<H1; d+=128) g_wbuf[(long)s*H1+d] = c2v*shh[d];
}

// ---------------- Kernel D: H = sum_s wbuf[s]; logits ----------------
__global__ __launch_bounds__(320) void final_kernel(
    const float* __restrict__ We, const float* __restrict__ be,
    const float* __restrict__ Ws, const float* __restrict__ bs,
    float* __restrict__ dout)
{
  __shared__ float sH[H1];
  int tid = threadIdx.x;
  if (tid < H1){
    float a0=0,a1=0,a2=0,a3=0;
    for (int s=0;s<SEQ;s+=4){
      a0 += g_wbuf[(long)(s+0)*H1+tid];
      a1 += g_wbuf[(long)(s+1)*H1+tid];
      a2 += g_wbuf[(long)(s+2)*H1+tid];
      a3 += g_wbuf[(long)(s+3)*H1+tid];
    }
    sH[tid] = (a0+a1)+(a2+a3);
  }
  __syncthreads();
  if (tid < 9){
    float r = (tid<8)? be[tid] : bs[0];
    for (int d=0; d<H1; d++){
      float wv = (tid<8)? We[d*8+tid] : Ws[d];
      r += sH[d]*wv;
    }
    dout[tid] = r;
  }
}

// ---------------- launch ----------------
extern "C" void kernel_launch(void* const* d_in, const int* in_sizes, int n_in,
                              void* d_out, int out_size)
{
  const int*   sentence = (const int*)d_in[0];
  const int*   syn_idx  = (const int*)d_in[1];
  const float* E    = (const float*)d_in[2];
  const float* Wk_f = (const float*)d_in[3];
  const float* Wr_f = (const float*)d_in[4];
  const float* b_f  = (const float*)d_in[5];
  const float* Wk_b = (const float*)d_in[6];
  const float* Wr_b = (const float*)d_in[7];
  const float* b_b  = (const float*)d_in[8];
  const float* W1   = (const float*)d_in[9];
  const float* b1   = (const float*)d_in[10];
  const float* W2   = (const float*)d_in[11];
  const float* b2   = (const float*)d_in[12];
  const float* We   = (const float*)d_in[13];
  const float* be   = (const float*)d_in[14];
  const float* Ws   = (const float*)d_in[15];
  const float* bs   = (const float*)d_in[16];
  float* dout = (float*)d_out;

  dim3 gA(SEQ/TS, 2);
  proj_kernel<<<gA, 608>>>(sentence, E, Wk_f, b_f, Wk_b, b_b);
  lstm_kernel<<<4, 320>>>(Wr_f, Wr_b);           // 2 clusters of 2 (fwd, bwd)
  out_kernel<<<SEQ/TS, 320>>>(W1, b1);
  attn_kernel<<<SEQ, 128>>>(sentence, syn_idx, E, W2, b2);
  final_kernel<<<1, 320>>>(We, be, Ws, bs, dout);
}

// round 3
// speedup vs baseline: 1.9452x; 1.5801x over previous
#include <cuda_runtime.h>
#include <cstdint>

#define SEQ   2048
#define D_IN  300
#define UDIM  150
#define ZDIM  600
#define H1    300
#define NSYN  4
#define TS    16

// ---------------- scratch (no cudaMalloc allowed) ----------------
__device__ float g_X[2][SEQ*ZDIM];     // x@Wk + b, per direction
__device__ float g_hidden[SEQ*H1];     // [hf | hb]
__device__ float g_out[SEQ*H1];        // hidden@W1 + b1
__device__ float g_wbuf[SEQ*H1];       // c2[s]*h_hat[s]

__device__ __forceinline__ uint32_t smem_u32(const void* p){
  uint32_t a;
  asm("{ .reg .u64 t; cvta.to.shared.u64 t, %1; cvt.u32.u64 %0, t; }" : "=r"(a) : "l"(p));
  return a;
}
__device__ __forceinline__ uint64_t ffma2(uint64_t a, uint64_t b, uint64_t c){
  uint64_t d; asm("fma.rn.f32x2 %0,%1,%2,%3;" : "=l"(d) : "l"(a),"l"(b),"l"(c)); return d;
}
__device__ __forceinline__ float sigm(float x){ return __fdividef(1.f, 1.f + __expf(-x)); }
__device__ __forceinline__ float tanh_(float x){ return 1.f - __fdividef(2.f, __expf(2.f*x)+1.f); }

// ---------------- Kernel A: X[dir] = emb@Wk_dir + b_dir ----------------
__global__ __launch_bounds__(608) void proj_kernel(
    const int* __restrict__ sentence,
    const float* __restrict__ E,
    const float* __restrict__ Wk_f, const float* __restrict__ b_f,
    const float* __restrict__ Wk_b, const float* __restrict__ b_b)
{
  int dir = blockIdx.y;
  const float* __restrict__ Wk = dir ? Wk_b : Wk_f;
  const float* __restrict__ bb = dir ? b_b : b_f;
  __shared__ __align__(16) float semb[TS*D_IN];
  __shared__ int srow[TS];
  int tid = threadIdx.x;
  int t0 = blockIdx.x * TS;
  if (tid < TS) srow[tid] = sentence[t0 + tid];
  __syncthreads();
  for (int e = tid; e < TS*D_IN; e += blockDim.x) {
    int s = e / D_IN, d = e - s*D_IN;
    semb[e] = E[(long)srow[s]*D_IN + d];
  }
  __syncthreads();
  if (tid >= ZDIM) return;
  int col = tid;
  float acc[TS];
  float bv = bb[col];
  #pragma unroll
  for (int s=0;s<TS;s++) acc[s]=bv;
  for (int k=0;k<D_IN;k+=4){
    float w0 = Wk[(k+0)*ZDIM+col];
    float w1 = Wk[(k+1)*ZDIM+col];
    float w2 = Wk[(k+2)*ZDIM+col];
    float w3 = Wk[(k+3)*ZDIM+col];
    #pragma unroll
    for (int s=0;s<TS;s++){
      float4 e4 = *reinterpret_cast<const float4*>(&semb[s*D_IN+k]);
      acc[s] += e4.x*w0 + e4.y*w1 + e4.z*w2 + e4.w*w3;
    }
  }
  #pragma unroll
  for (int s=0;s<TS;s++)
    g_X[dir][(long)(t0+s)*ZDIM + col] = acc[s];
}

// ---------------- LSTM: cluster of 2 CTAs per direction ----------------
// 300 compute threads per CTA; thread c owns z-column G = gate*150 + rank*75 + u
// with all 150 recurrent weights in registers as 76 packed f32x2 pairs.
// h handoff via st.async + mbarrier transaction counts (no arrive storm,
// CTA-scope acquire on the wait).
struct LSmem2 {
  float4 h[2][38];        // double-buffered h[152] (150 + 2 zero pad)
  float  z[304];
  unsigned long long mbar;
};

__global__ void __cluster_dims__(2,1,1) __launch_bounds__(320,1)
lstm_kernel(const float* __restrict__ Wr_f, const float* __restrict__ Wr_b)
{
  __shared__ LSmem2 sm;
  int tid = threadIdx.x;
  int dir = blockIdx.x >> 1;
  uint32_t rank;
  asm("mov.u32 %0, %%cluster_ctarank;" : "=r"(rank));
  uint32_t peer = rank ^ 1u;
  const float* __restrict__ Wr = dir ? Wr_b : Wr_f;
  const float* __restrict__ X  = g_X[dir];

  bool active = tid < 300;
  int gate = tid / 75;
  int u    = tid - gate*75;
  int G    = gate*150 + (int)rank*75 + u;   // global z column

  // pack recurrent weights: pair m = (Wr[2m][G], Wr[2m+1][G])
  uint64_t w2[76];
  if (active){
    #pragma unroll
    for (int m=0;m<76;m++){
      float w0 = (2*m   < UDIM) ? Wr[(2*m  )*ZDIM + G] : 0.f;
      float w1 = (2*m+1 < UDIM) ? Wr[(2*m+1)*ZDIM + G] : 0.f;
      asm("mov.b64 %0,{%1,%2};" : "=l"(w2[m]) : "f"(w0), "f"(w1));
    }
  }

  float* hraw = (float*)sm.h;
  for (int i=tid;i<2*152;i+=320) hraw[i]=0.f;

  uint32_t s_h    = smem_u32(&sm.h[0][0]);
  uint32_t s_mbar = smem_u32(&sm.mbar);
  if (tid == 0){
    asm volatile("mbarrier.init.shared.b64 [%0], %1;" :: "r"(s_mbar), "r"(1) : "memory");
  }
  __syncthreads();

  // cluster-ranked addresses for own and peer CTA (st.async needs
  // shared::cluster addressing; mbar must be co-located with the dst)
  uint32_t o_h, o_mbar, r_h, r_mbar;
  asm("mapa.shared::cluster.u32 %0, %1, %2;" : "=r"(o_h)    : "r"(s_h),    "r"(rank));
  asm("mapa.shared::cluster.u32 %0, %1, %2;" : "=r"(o_mbar) : "r"(s_mbar), "r"(rank));
  asm("mapa.shared::cluster.u32 %0, %1, %2;" : "=r"(r_h)    : "r"(s_h),    "r"(peer));
  asm("mapa.shared::cluster.u32 %0, %1, %2;" : "=r"(r_mbar) : "r"(s_mbar), "r"(peer));

  // one-time cluster sync: peer smem (h zeros, mbar) initialized
  asm volatile("barrier.cluster.arrive.aligned;" ::: "memory");
  asm volatile("barrier.cluster.wait.aligned;"   ::: "memory");

  float creg = 0.f;
  float x = 0.f;
  if (active) x = __ldg(&X[(dir ? (SEQ-1) : 0)*ZDIM + G]);

  for (int ts=0; ts<SEQ; ts++){
    int rb = ts & 1;

    // one arrival + 600B (150 h floats: 75 local + 75 from peer) per phase
    if (tid == 0){
      asm volatile("mbarrier.arrive.expect_tx.shared.b64 _, [%0], %1;"
                   :: "r"(s_mbar), "r"(600) : "memory");
    }

    uint64_t a0=0ull, a1=0ull, a2=0ull, a3=0ull;
    if (active){
      uint32_t ha = s_h + rb*608;   // 152 floats * 4B
      #pragma unroll
      for (int m=0;m<38;m++){
        uint64_t p0,p1;
        asm("ld.shared.v2.b64 {%0,%1},[%2];" : "=l"(p0),"=l"(p1) : "r"(ha + m*16));
        if (m & 1){ a2 = ffma2(p0, w2[2*m], a2); a3 = ffma2(p1, w2[2*m+1], a3); }
        else      { a0 = ffma2(p0, w2[2*m], a0); a1 = ffma2(p1, w2[2*m+1], a1); }
      }
      float l0,h0,l1,h1,l2,h2,l3,h3;
      asm("mov.b64 {%0,%1},%2;" : "=f"(l0),"=f"(h0) : "l"(a0));
      asm("mov.b64 {%0,%1},%2;" : "=f"(l1),"=f"(h1) : "l"(a1));
      asm("mov.b64 {%0,%1},%2;" : "=f"(l2),"=f"(h2) : "l"(a2));
      asm("mov.b64 {%0,%1},%2;" : "=f"(l3),"=f"(h3) : "l"(a3));
      sm.z[tid] = x + ((l0+h0)+(l1+h1)) + ((l2+h2)+(l3+h3));
    }
    // prefetch next step's x while z settles (hides L2 latency behind sync)
    if (active && ts+1 < SEQ){
      int tn = dir ? (SEQ-2-ts) : (ts+1);
      x = __ldg(&X[tn*ZDIM + G]);
    }
    __syncthreads();

    if (tid < 75){
      float zi = sm.z[tid];
      float zf = sm.z[75+tid];
      float zg = sm.z[150+tid];
      float zo = sm.z[225+tid];
      float ig = sigm(zi);
      float fg = sigm(zf);
      float gg = tanh_(zg);
      float og = sigm(zo);
      creg = fg*creg + ig*gg;
      float h = og*tanh_(creg);
      int wb = rb ^ 1;
      int hi = (int)rank*75 + tid;
      uint32_t off = (uint32_t)(wb*608 + hi*4);
      // h -> own CTA buffer and peer CTA buffer, each signaling that CTA's mbar
      asm volatile("st.async.shared::cluster.mbarrier::complete_tx::bytes.f32 [%0], %1, [%2];"
                   :: "r"(o_h + off), "f"(h), "r"(o_mbar) : "memory");
      asm volatile("st.async.shared::cluster.mbarrier::complete_tx::bytes.f32 [%0], %1, [%2];"
                   :: "r"(r_h + off), "f"(h), "r"(r_mbar) : "memory");
      int t = dir ? (SEQ-1-ts) : ts;
      g_hidden[t*H1 + dir*UDIM + hi] = h;
    }

    // wait for this step's phase (CTA-scope acquire; async-proxy tx makes
    // the h stores visible on completion)
    {
      uint32_t done;
      asm volatile(
        "{\n\t.reg .pred p;\n\t"
        "mbarrier.try_wait.parity.acquire.cta.shared::cta.b64 p, [%1], %2;\n\t"
        "selp.b32 %0, 1, 0, p;\n\t}"
        : "=r"(done) : "r"(s_mbar), "r"((uint32_t)rb) : "memory");
      if (!done){
        asm volatile(
          "{\n\t.reg .pred P1;\n\t"
          "W_%=:\n\t"
          "mbarrier.try_wait.parity.acquire.cta.shared::cta.b64 P1, [%0], %1, 0x989680;\n\t"
          "@P1 bra.uni D_%=;\n\t"
          "bra.uni W_%=;\n\t"
          "D_%=:\n\t}"
          :: "r"(s_mbar), "r"((uint32_t)rb) : "memory");
      }
    }
  }
}

// ---------------- Kernel B: out = hidden@W1 + b1 ----------------
__global__ __launch_bounds__(320) void out_kernel(
    const float* __restrict__ W1, const float* __restrict__ b1)
{
  __shared__ __align__(16) float shid[TS*H1];
  int tid = threadIdx.x;
  int t0 = blockIdx.x * TS;
  for (int e=tid; e<TS*H1; e+=blockDim.x)
    shid[e] = g_hidden[(long)t0*H1 + e];
  __syncthreads();
  if (tid >= H1) return;
  int col = tid;
  float acc[TS];
  float bv = b1[col];
  #pragma unroll
  for (int s=0;s<TS;s++) acc[s]=bv;
  for (int k=0;k<H1;k+=4){
    float w0=W1[(k+0)*H1+col], w1=W1[(k+1)*H1+col];
    float w2=W1[(k+2)*H1+col], w3=W1[(k+3)*H1+col];
    #pragma unroll
    for (int s=0;s<TS;s++){
      float4 e4 = *reinterpret_cast<const float4*>(&shid[s*H1+k]);
      acc[s] += e4.x*w0+e4.y*w1+e4.z*w2+e4.w*w3;
    }
  }
  #pragma unroll
  for (int s=0;s<TS;s++) g_out[(long)(t0+s)*H1+col]=acc[s];
}

// ---------------- Kernel C: synonym attention per token ----------------
__global__ __launch_bounds__(128) void attn_kernel(
    const int* __restrict__ sentence,
    const int* __restrict__ syn_idx,
    const float* __restrict__ E,
    const float* __restrict__ W2, const float* __restrict__ b2)
{
  int s = blockIdx.x;
  int ids = (s==0)?0:(s-1);
  int tid = threadIdx.x;
  __shared__ float sout[H1], ssyn[NSYN*H1], shh[H1], red[128], scoef[NSYN], sc2;
  __shared__ int srow[NSYN];
  int token = sentence[s];
  if (tid < NSYN) srow[tid] = syn_idx[token*NSYN+tid];
  for (int d=tid; d<H1; d+=128) sout[d] = g_out[(long)ids*H1+d];
  __syncthreads();
  for (int e=tid; e<NSYN*H1; e+=128){
    int k=e/H1, d=e-k*H1;
    ssyn[e] = E[(long)srow[k]*D_IN + d];
  }
  __syncthreads();
  float p0=0,p1=0,p2=0,p3=0;
  for (int d=tid; d<H1; d+=128){
    float o = sout[d];
    p0 += ssyn[d]*o; p1 += ssyn[H1+d]*o; p2 += ssyn[2*H1+d]*o; p3 += ssyn[3*H1+d]*o;
  }
  float pv[4]={p0,p1,p2,p3};
  #pragma unroll
  for (int k=0;k<4;k++){
    red[tid]=pv[k]; __syncthreads();
    for (int off=64; off>0; off>>=1){
      if(tid<off) red[tid]+=red[tid+off];
      __syncthreads();
    }
    if (tid==0) scoef[k]=expf(red[0]);
    __syncthreads();
  }
  float q=0.f;
  for (int d=tid; d<H1; d+=128){
    float hh = scoef[0]*ssyn[d]+scoef[1]*ssyn[H1+d]
             + scoef[2]*ssyn[2*H1+d]+scoef[3]*ssyn[3*H1+d]
             + g_hidden[(long)ids*H1+d];
    shh[d]=hh;
    q += hh*W2[d];
  }
  red[tid]=q; __syncthreads();
  for (int off=64; off>0; off>>=1){
    if(tid<off) red[tid]+=red[tid+off];
    __syncthreads();
  }
  if (tid==0) sc2 = expf(tanhf(red[0]+b2[0]));
  __syncthreads();
  float c2v = sc2;
  for (int d=tid; d<H1; d+=128) g_wbuf[(long)s*H1+d] = c2v*shh[d];
}

// ---------------- Kernel D: H = sum_s wbuf[s]; logits ----------------
__global__ __launch_bounds__(320) void final_kernel(
    const float* __restrict__ We, const float* __restrict__ be,
    const float* __restrict__ Ws, const float* __restrict__ bs,
    float* __restrict__ dout)
{
  __shared__ float sH[H1];
  int tid = threadIdx.x;
  if (tid < H1){
    float a0=0,a1=0,a2=0,a3=0;
    for (int s=0;s<SEQ;s+=4){
      a0 += g_wbuf[(long)(s+0)*H1+tid];
      a1 += g_wbuf[(long)(s+1)*H1+tid];
      a2 += g_wbuf[(long)(s+2)*H1+tid];
      a3 += g_wbuf[(long)(s+3)*H1+tid];
    }
    sH[tid] = (a0+a1)+(a2+a3);
  }
  __syncthreads();
  if (tid < 9){
    float r = (tid<8)? be[tid] : bs[0];
    for (int d=0; d<H1; d++){
      float wv = (tid<8)? We[d*8+tid] : Ws[d];
      r += sH[d]*wv;
    }
    dout[tid] = r;
  }
}

// ---------------- launch ----------------
extern "C" void kernel_launch(void* const* d_in, const int* in_sizes, int n_in,
                              void* d_out, int out_size)
{
  const int*   sentence = (const int*)d_in[0];
  const int*   syn_idx  = (const int*)d_in[1];
  const float* E    = (const float*)d_in[2];
  const float* Wk_f = (const float*)d_in[3];
  const float* Wr_f = (const float*)d_in[4];
  const float* b_f  = (const float*)d_in[5];
  const float* Wk_b = (const float*)d_in[6];
  const float* Wr_b = (const float*)d_in[7];
  const float* b_b  = (const float*)d_in[8];
  const float* W1   = (const float*)d_in[9];
  const float* b1   = (const float*)d_in[10];
  const float* W2   = (const float*)d_in[11];
  const float* b2   = (const float*)d_in[12];
  const float* We   = (const float*)d_in[13];
  const float* be   = (const float*)d_in[14];
  const float* Ws   = (const float*)d_in[15];
  const float* bs   = (const float*)d_in[16];
  float* dout = (float*)d_out;

  dim3 gA(SEQ/TS, 2);
  proj_kernel<<<gA, 608>>>(sentence, E, Wk_f, b_f, Wk_b, b_b);
  lstm_kernel<<<4, 320>>>(Wr_f, Wr_b);           // 2 clusters of 2 (fwd, bwd)
  out_kernel<<<SEQ/TS, 320>>>(W1, b1);
  attn_kernel<<<SEQ, 128>>>(sentence, syn_idx, E, W2, b2);
  final_kernel<<<1, 320>>>(We, be, Ws, bs, dout);
}